// round 8
// baseline (speedup 1.0000x reference)
#include <cuda_runtime.h>

#define BATCH 128
#define SITES 256
#define BOND 64
#define NOUT 10
#define HALFS 128            // sites per half
#define NPAIRS 64            // site pairs per half
#define SITE_BYTES 32768     // 64*64*2 floats
#define PAIR_BYTES 65536     // 2 sites per TMA stage
#define STAGES 3             // 3 * 64KB ring
#define CLUSTER 4

typedef unsigned long long ull;

// Scratch (device globals — no allocation allowed)
__device__ __align__(16) float g_ct[HALFS * BOND * BOND * 2]; // right half, transposed+reversed
__device__ float g_vL[BATCH * BOND];
__device__ float g_wR[BATCH * BOND];

// ---- packed f32x2 helpers ----
static __device__ __forceinline__ ull ffma2(ull a, ull b, ull c) {
    ull d;
    asm("fma.rn.f32x2 %0, %1, %2, %3;" : "=l"(d) : "l"(a), "l"(b), "l"(c));
    return d;
}
static __device__ __forceinline__ ull fadd2(ull a, ull b) {
    ull d;
    asm("add.rn.f32x2 %0, %1, %2;" : "=l"(d) : "l"(a), "l"(b));
    return d;
}
static __device__ __forceinline__ float f2lo(ull v) {
    return __uint_as_float((unsigned)(v & 0xffffffffull));
}
static __device__ __forceinline__ float f2hi(ull v) {
    return __uint_as_float((unsigned)(v >> 32));
}
static __device__ __forceinline__ ull dup2(float v) {
    unsigned u = __float_as_uint(v);
    return ((ull)u << 32) | u;
}
static __device__ __forceinline__ unsigned smem_u32(const void* p) {
    return (unsigned)__cvta_generic_to_shared(p);
}
static __device__ __forceinline__ unsigned cluster_rank() {
    unsigned r;
    asm("mov.u32 %0, %%cluster_ctarank;" : "=r"(r));
    return r;
}

// ---- mbarrier / bulk-copy primitives ----
static __device__ __forceinline__ void mbar_init(unsigned addr, unsigned count) {
    asm volatile("mbarrier.init.shared.b64 [%0], %1;" :: "r"(addr), "r"(count) : "memory");
}
static __device__ __forceinline__ void mbar_expect_tx(unsigned addr, unsigned bytes) {
    asm volatile("mbarrier.arrive.expect_tx.shared.b64 _, [%0], %1;"
                 :: "r"(addr), "r"(bytes) : "memory");
}
static __device__ __forceinline__ void mbar_wait(unsigned addr, unsigned parity) {
    asm volatile(
        "{\n\t"
        ".reg .pred P;\n\t"
        "WAIT_%=:\n\t"
        "mbarrier.try_wait.parity.acquire.cta.shared::cta.b64 P, [%0], %1, 0x989680;\n\t"
        "@P bra.uni DONE_%=;\n\t"
        "bra.uni WAIT_%=;\n\t"
        "DONE_%=:\n\t"
        "}"
        :: "r"(addr), "r"(parity) : "memory");
}
// Multicast bulk copy: rank0 issues; data + complete_tx delivered to the same
// SMEM/mbar offsets in every CTA whose bit is set in mask.
static __device__ __forceinline__ void bulk_g2s_mc(unsigned dst, const void* src,
                                                   unsigned bytes, unsigned mbar,
                                                   unsigned short mask) {
    asm volatile(
        "cp.async.bulk.shared::cluster.global.mbarrier::complete_tx::bytes.multicast::cluster"
        " [%0], [%1], %2, [%3], %4;"
        :: "r"(dst), "l"(src), "r"(bytes), "r"(mbar), "h"(mask) : "memory");
}
// Arrive on the mbarrier at the same SMEM offset in cluster CTA 0.
static __device__ __forceinline__ void mbar_arrive_cta0(unsigned local_addr) {
    asm volatile(
        "{\n\t"
        ".reg .b32 ra;\n\t"
        "mapa.shared::cluster.u32 ra, %0, 0;\n\t"
        "mbarrier.arrive.shared::cluster.b64 _, [ra];\n\t"
        "}"
        :: "r"(local_addr) : "memory");
}
static __device__ __forceinline__ void cluster_sync() {
    asm volatile("barrier.cluster.arrive.aligned;" ::: "memory");
    asm volatile("barrier.cluster.wait.aligned;" ::: "memory");
}

// ============================================================
// Kernel 1: repack right-half cores only.
// g_ct[t][r][2l+i] = cores[255 - t][l][r][i]  (transpose, reverse order)
// ============================================================
__global__ void __launch_bounds__(256) repack_kernel(const float* __restrict__ cores) {
    int t = blockIdx.x;            // 0..127
    int s = 255 - t;
    __shared__ float2 sh[64 * 65];
    const float2* src = (const float2*)cores + (size_t)s * 4096; // [l*64 + r] -> (c0,c1)
    float2* dst = (float2*)g_ct + (size_t)t * 4096;              // [r*64 + l]
    for (int idx = threadIdx.x; idx < 4096; idx += blockDim.x) {
        int l = idx >> 6, r = idx & 63;
        sh[r * 65 + l] = src[idx];
    }
    __syncthreads();
    for (int idx = threadIdx.x; idx < 4096; idx += blockDim.x) {
        int r = idx >> 6, l = idx & 63;
        dst[idx] = sh[r * 65 + l];
    }
}

// ============================================================
// Kernel 2: vector chains. One warp per block, 2 chains per warp.
// grid (64, 2) = 128 blocks, clusters of 4 along x (same half).
// All 4 CTAs of a cluster consume the SAME tile stream: rank0 issues
// one multicast bulk copy per 64KB stage (2 sites), cutting L2 reads 4x.
// Backpressure: empty mbar (count=4) in rank0 SMEM; producer waits it
// one pair ahead of stage reuse.
// State double-buffered in shared for cross-lane broadcast; each lane's
// own 4 state scalars additionally live in registers (short tail).
// ============================================================
__global__ void __launch_bounds__(32) __cluster_dims__(CLUSTER, 1, 1)
chain_kernel(
    const float* __restrict__ x,      // [B][S][2]
    const float* __restrict__ cores,  // [S][l][r][2]
    const float* __restrict__ lvec,
    const float* __restrict__ rvec)
{
    extern __shared__ __align__(128) char dynsmem[];   // STAGES * 64KB
    __shared__ __align__(16) ull st[2][2][64];         // [buf][chain][j] = (v,v)
    __shared__ __align__(16) float2 sx[2][HALFS];      // per-chain x, site order
    __shared__ __align__(8) ull full_store[STAGES];
    __shared__ __align__(8) ull empty_store[STAGES];

    const int lane = threadIdx.x;
    const int half = blockIdx.y;
    const int o0   = 2 * lane;
    const unsigned rank = cluster_rank();

    unsigned fmb[STAGES], emb[STAGES];
    #pragma unroll
    for (int si = 0; si < STAGES; ++si) {
        fmb[si] = smem_u32(&full_store[si]);
        emb[si] = smem_u32(&empty_store[si]);
    }
    if (lane == 0) {
        #pragma unroll
        for (int si = 0; si < STAGES; ++si) {
            mbar_init(fmb[si], 1);
            mbar_init(emb[si], CLUSTER);
        }
        // expect the three primed stages before cluster_sync
        #pragma unroll
        for (int si = 0; si < STAGES; ++si) mbar_expect_tx(fmb[si], PAIR_BYTES);
    }

    // Stage per-chain x values (site order t).
    for (int i = lane; i < 2 * HALFS; i += 32) {
        int c = i >> 7, t = i & 127;
        int batch = blockIdx.x * 2 + c;
        int s = half ? (255 - t) : t;
        sx[c][t] = *(const float2*)(x + ((size_t)batch * SITES + s) * 2);
    }
    // Init state: regs + shared buffer 0.
    const float* bv = half ? rvec : lvec;
    float rA0 = bv[o0], rA1 = bv[o0 + 1];
    float rB0 = rA0,    rB1 = rA1;
    st[0][0][o0] = dup2(rA0); st[0][0][o0 + 1] = dup2(rA1);
    st[0][1][o0] = dup2(rB0); st[0][1][o0 + 1] = dup2(rB1);

    cluster_sync();  // mbars init + expects visible cluster-wide

    const char* gsrc = half ? (const char*)g_ct : (const char*)cores;

    // Prime: rank0 multicasts stage-pairs 0..2 to the whole cluster.
    if (rank == 0 && lane == 0) {
        #pragma unroll
        for (int pr = 0; pr < STAGES; ++pr)
            bulk_g2s_mc(smem_u32(dynsmem + (size_t)pr * PAIR_BYTES),
                        gsrc + (size_t)pr * PAIR_BYTES, PAIR_BYTES, fmb[pr],
                        (unsigned short)((1u << CLUSTER) - 1u));
    }

    for (int t = 0; t < HALFS; ++t) {
        const int pair = t >> 1;
        const int stg  = pair % STAGES;

        if ((t & 1) == 0) {
            // Producer: refill stage for pair+2 (holds pair-1, freed by all CTAs).
            if (rank == 0 && lane == 0 && pair >= 1 && pair + 2 < NPAIRS) {
                const int s2 = (pair + 2) % STAGES;
                mbar_wait(emb[s2], ((pair - 1) / STAGES) & 1);
                bulk_g2s_mc(smem_u32(dynsmem + (size_t)s2 * PAIR_BYTES),
                            gsrc + (size_t)(pair + 2) * PAIR_BYTES, PAIR_BYTES, fmb[s2],
                            (unsigned short)((1u << CLUSTER) - 1u));
            }
            mbar_wait(fmb[stg], (pair / STAGES) & 1);
        }

        const int cur = t & 1;  // state read buffer; write buffer = cur^1
        const ulonglong2* tp =
            (const ulonglong2*)(dynsmem + (size_t)stg * PAIR_BYTES + (size_t)cur * SITE_BYTES)
            + lane;
        const ulonglong2* sA = (const ulonglong2*)&st[cur][0][0];
        const ulonglong2* sB = (const ulonglong2*)&st[cur][1][0];

        ull a0 = 0, a1 = 0, a2 = 0, a3 = 0;   // chain A
        ull b0 = 0, b1 = 0, b2 = 0, b3 = 0;   // chain B
        #pragma unroll
        for (int jj = 0; jj < 32; ++jj) {
            ulonglong2 ca = tp[(2 * jj) * 32];       // row 2jj:  (c0,c1) for o0 | o0+1
            ulonglong2 cb = tp[(2 * jj + 1) * 32];   // row 2jj+1
            ulonglong2 vA = sA[jj];                  // broadcast state pairs
            ulonglong2 vB = sB[jj];
            a0 = ffma2(ca.x, vA.x, a0);
            a1 = ffma2(ca.y, vA.x, a1);
            a2 = ffma2(cb.x, vA.y, a2);
            a3 = ffma2(cb.y, vA.y, a3);
            b0 = ffma2(ca.x, vB.x, b0);
            b1 = ffma2(ca.y, vB.x, b1);
            b2 = ffma2(cb.x, vB.y, b2);
            b3 = ffma2(cb.y, vB.y, b3);
        }
        ull dA0 = fadd2(a0, a2);   // (dot_f0, dot_f1) chain A, output o0
        ull dA1 = fadd2(a1, a3);
        ull dB0 = fadd2(b0, b2);
        ull dB1 = fadd2(b1, b3);

        const float2 xA = sx[0][t];
        const float2 xB = sx[1][t];
        rA0 = fmaf(xA.x, f2lo(dA0), fmaf(xA.y, f2hi(dA0), rA0));
        rA1 = fmaf(xA.x, f2lo(dA1), fmaf(xA.y, f2hi(dA1), rA1));
        rB0 = fmaf(xB.x, f2lo(dB0), fmaf(xB.y, f2hi(dB0), rB0));
        rB1 = fmaf(xB.x, f2lo(dB1), fmaf(xB.y, f2hi(dB1), rB1));

        ulonglong2* wA = (ulonglong2*)&st[cur ^ 1][0][o0];
        ulonglong2* wB = (ulonglong2*)&st[cur ^ 1][1][o0];
        *wA = make_ulonglong2(dup2(rA0), dup2(rA1));
        *wB = make_ulonglong2(dup2(rB0), dup2(rB1));
        __syncwarp();

        // End of a pair: set expect for pair+3's reuse of this stage, then
        // release the stage to the producer (cluster CTA 0).
        if ((t & 1) == 1 && lane == 0 && pair + STAGES < NPAIRS) {
            mbar_expect_tx(fmb[stg], PAIR_BYTES);
            mbar_arrive_cta0(emb[stg]);
        }
    }

    // Final state is in registers.
    float* dst = half ? g_wR : g_vL;
    const int bA = blockIdx.x * 2;
    dst[bA * 64 + o0]           = rA0;
    dst[bA * 64 + o0 + 1]       = rA1;
    dst[(bA + 1) * 64 + o0]     = rB0;
    dst[(bA + 1) * 64 + o0 + 1] = rB1;

    cluster_sync();  // no CTA exits while peer-targeted arrives may be in flight
}

// ============================================================
// Kernel 3: logits[b][o] = sum_{l,r} vL[l] * oc[o][l][r] * wR[r]
// ============================================================
__global__ void __launch_bounds__(64) combine_kernel(
    const float* __restrict__ oc, float* __restrict__ out)
{
    const int b = blockIdx.x;
    const int tid = threadIdx.x; // 0..63 = r
    __shared__ float vL[64], wR[64];
    __shared__ float red[2];
    vL[tid] = g_vL[b * 64 + tid];
    wR[tid] = g_wR[b * 64 + tid];
    __syncthreads();
    const float w = wR[tid];
    for (int o = 0; o < NOUT; ++o) {
        float acc = 0.f;
        const float* row = oc + (size_t)o * 4096 + tid;
        #pragma unroll 16
        for (int l = 0; l < 64; ++l)
            acc = fmaf(vL[l], row[(size_t)l * 64], acc);
        float pv = acc * w;
        #pragma unroll
        for (int off = 16; off; off >>= 1)
            pv += __shfl_down_sync(0xffffffffu, pv, off);
        if ((tid & 31) == 0) red[tid >> 5] = pv;
        __syncthreads();
        if (tid == 0) out[b * NOUT + o] = red[0] + red[1];
        __syncthreads();
    }
}

extern "C" void kernel_launch(void* const* d_in, const int* in_sizes, int n_in,
                              void* d_out, int out_size) {
    const float* input_data = (const float*)d_in[0]; // [128,256,2]
    const float* cores      = (const float*)d_in[1]; // [256,64,64,2]
    const float* out_core   = (const float*)d_in[2]; // [10,64,64]
    const float* lvec       = (const float*)d_in[3]; // [64]
    const float* rvec       = (const float*)d_in[4]; // [64]
    float* out = (float*)d_out;                      // [128,10]

    cudaFuncSetAttribute(chain_kernel,
                         cudaFuncAttributeMaxDynamicSharedMemorySize,
                         STAGES * PAIR_BYTES);

    repack_kernel<<<HALFS, 256>>>(cores);
    chain_kernel<<<dim3(64, 2), 32, STAGES * PAIR_BYTES>>>(input_data, cores, lvec, rvec);
    combine_kernel<<<BATCH, 64>>>(out_core, out);
}